// round 9
// baseline (speedup 1.0000x reference)
#include <cuda_runtime.h>
#include <cstdint>

// Problem constants
#define Bn   4
#define Cn   16
#define Hn   800
#define Wn   1200
#define HWn  (Hn * Wn)          // 960000
#define HFn  200                 // H/4
#define WFn  200                 // W/6
#define NPIX (512 * 512)         // 262144

// Part -> source selection: parts {1, 14..21} come from source_feature
#define SRC_MASK 0x003FC002u
// Apparel classes: cls==2 or 15<=cls<=22  -> bits 2, 15..22
#define APP_MASK 0x007F8004u

// XLA lowering of (x*199)/255: divide -> multiply by fl(1/255) = 0x3B808081,
// multiplies NOT reassociated (verified bit-exact in R3).
__device__ __forceinline__ float recip255() {
    return __uint_as_float(0x3B808081u);
}

// ---------------------------------------------------------------------------
// Fused gather kernel (R4 structure, best so far):
//  - 1 pixel / thread, 256 threads, plain loads/stores for streaming traffic
//  - gathers use __ldcg: cache at L2 only, skip L1 allocate. Random gathers
//    have ~0% L1 hit rate; skipping L1 fills removes fill/evict work from the
//    L1tex pipe, which is the co-binding constraint (61% busy).
// ---------------------------------------------------------------------------
__global__ __launch_bounds__(256) void k_fused(
    const float* __restrict__ sf,    // source_feature [B,16,H,W]
    const float* __restrict__ tf,    // target_feature [B,16,H,W]
    const float* __restrict__ dp,    // dense_pose [B,512,512,3]
    const float* __restrict__ st,    // source_texture [B,3,H,W]
    const float* __restrict__ timg,  // target_image [B,3,512,512]
    float* __restrict__ out)         // [B,19,512,512]
{
    const int b   = blockIdx.y;
    const int pix = blockIdx.x * 256 + threadIdx.x;   // 0 .. NPIX-1

    const float* d = dp + ((size_t)b * NPIX + pix) * 3;
    const float clsf = d[0];
    const float U    = d[1];
    const float V    = d[2];

    const int  cls   = (int)clsf;
    const bool valid = (cls >= 1) && (V != 0.0f);

    int p = cls - 1;
    p = p < 0 ? 0 : (p > 23 ? 23 : p);

    const float R = recip255();
    // XLA: t = RN(x*199); idx = trunc(RN(t * fl(1/255)))
    const int ui = (int)__fmul_rn(__fmul_rn(U, 199.0f), R);
    const int vi = (int)__fmul_rn(__fmul_rn(__fsub_rn(255.0f, V), 199.0f), R);

    const int tr  = p / 6;
    const int tc  = p - tr * 6;
    const int pos = (tr * HFn + ui) * Wn + (tc * WFn + vi);

    // Union selection: which tensor does this PART come from
    const bool use_src = (SRC_MASK >> p) & 1u;
    const float* fbase = (use_src ? sf : tf) + (size_t)b * Cn * HWn + pos;

    const bool apparel = (APP_MASK >> cls) & 1u;   // implies cls != 0
    const bool bg      = (cls != 0);

    float v[16];
    float t0 = 0.f, t1 = 0.f, t2 = 0.f;
    if (valid) {
#pragma unroll
        for (int ch = 0; ch < 16; ch++)
            v[ch] = __ldcg(fbase + (size_t)ch * HWn);
        if (apparel) {
            const float* tb = st + (size_t)b * 3 * HWn + pos;
            t0 = __ldcg(tb);
            t1 = __ldcg(tb + HWn);
            t2 = __ldcg(tb + 2 * HWn);
        }
    } else {
#pragma unroll
        for (int ch = 0; ch < 16; ch++)
            v[ch] = 0.0f;
    }

    float* ob = out + (size_t)b * 19 * NPIX + pix;
#pragma unroll
    for (int ch = 0; ch < 16; ch++)
        ob[(size_t)ch * NPIX] = v[ch];

    if (apparel) {
        ob[16 * NPIX] = t0;
        ob[17 * NPIX] = t1;
        ob[18 * NPIX] = t2;
    } else if (bg) {
        const float* ti = timg + (size_t)b * 3 * NPIX + pix;
        ob[16 * NPIX] = __ldg(ti);
        ob[17 * NPIX] = __ldg(ti + NPIX);
        ob[18 * NPIX] = __ldg(ti + 2 * NPIX);
    } else {
        ob[16 * NPIX] = 0.0f;
        ob[17 * NPIX] = 0.0f;
        ob[18 * NPIX] = 0.0f;
    }
}

// ---------------------------------------------------------------------------
extern "C" void kernel_launch(void* const* d_in, const int* in_sizes, int n_in,
                              void* d_out, int out_size)
{
    const float* source_feature = (const float*)d_in[0];
    const float* target_feature = (const float*)d_in[1];
    const float* dense_pose     = (const float*)d_in[2];
    const float* source_texture = (const float*)d_in[3];
    const float* target_image   = (const float*)d_in[4];
    float* out = (float*)d_out;

    dim3 g(NPIX / 256, Bn);
    k_fused<<<g, 256>>>(source_feature, target_feature, dense_pose,
                        source_texture, target_image, out);
}

// round 10
// speedup vs baseline: 1.1408x; 1.1408x over previous
#include <cuda_runtime.h>
#include <cstdint>

// Problem constants
#define Bn   4
#define Cn   16
#define Hn   800
#define Wn   1200
#define HWn  (Hn * Wn)          // 960000
#define HFn  200                 // H/4
#define WFn  200                 // W/6
#define NPIX (512 * 512)         // 262144
#define NGRP 4                   // channel groups (gridDim.z), 4 channels each

// Part -> source selection: parts {1, 14..21} come from source_feature
#define SRC_MASK 0x003FC002u
// Apparel classes: cls==2 or 15<=cls<=22  -> bits 2, 15..22
#define APP_MASK 0x007F8004u

// XLA lowering of (x*199)/255: divide -> multiply by fl(1/255) = 0x3B808081,
// multiplies NOT reassociated (verified bit-exact in R3).
__device__ __forceinline__ float recip255() {
    return __uint_as_float(0x3B808081u);
}

// ---------------------------------------------------------------------------
// Channel-split fused gather:
//   gridDim = (NPIX/256, B, NGRP). z (channel group) is the outermost launch
//   dimension, so all CTAs of one group co-run. Active gather footprint per
//   group = 4 planes x 4 batches ~ 60 MB -> fully L2-resident -> the ~4.4x
//   per-line reuse is captured instead of evicted.
//   Group 3 additionally produces the texture/composite channels 16..18.
// ---------------------------------------------------------------------------
__global__ __launch_bounds__(256) void k_split(
    const float* __restrict__ sf,    // source_feature [B,16,H,W]
    const float* __restrict__ tf,    // target_feature [B,16,H,W]
    const float* __restrict__ dp,    // dense_pose [B,512,512,3]
    const float* __restrict__ st,    // source_texture [B,3,H,W]
    const float* __restrict__ timg,  // target_image [B,3,512,512]
    float* __restrict__ out)         // [B,19,512,512]
{
    const int b   = blockIdx.y;
    const int g   = blockIdx.z;                        // channel group 0..3
    const int pix = blockIdx.x * 256 + threadIdx.x;    // 0 .. NPIX-1

    const float* d = dp + ((size_t)b * NPIX + pix) * 3;
    const float clsf = d[0];
    const float U    = d[1];
    const float V    = d[2];

    const int  cls   = (int)clsf;
    const bool valid = (cls >= 1) && (V != 0.0f);

    int p = cls - 1;
    p = p < 0 ? 0 : (p > 23 ? 23 : p);

    const float R = recip255();
    // XLA: t = RN(x*199); idx = trunc(RN(t * fl(1/255)))
    const int ui = (int)__fmul_rn(__fmul_rn(U, 199.0f), R);
    const int vi = (int)__fmul_rn(__fmul_rn(__fsub_rn(255.0f, V), 199.0f), R);

    const int tr  = p / 6;
    const int tc  = p - tr * 6;
    const int pos = (tr * HFn + ui) * Wn + (tc * WFn + vi);

    const bool use_src = (SRC_MASK >> p) & 1u;
    const int  ch0 = g * 4;
    const float* fbase = (use_src ? sf : tf)
                       + (size_t)b * Cn * HWn + (size_t)ch0 * HWn + pos;

    float v[4];
    if (valid) {
#pragma unroll
        for (int c = 0; c < 4; c++)
            v[c] = __ldg(fbase + (size_t)c * HWn);
    } else {
#pragma unroll
        for (int c = 0; c < 4; c++)
            v[c] = 0.0f;
    }

    float* ob = out + (size_t)b * 19 * NPIX + (size_t)ch0 * NPIX + pix;
#pragma unroll
    for (int c = 0; c < 4; c++)
        ob[(size_t)c * NPIX] = v[c];

    // Group 3 also produces channels 16..18 (texture composite)
    if (g == NGRP - 1) {
        const bool apparel = (APP_MASK >> cls) & 1u;   // implies cls != 0
        const bool bg      = (cls != 0);

        float* oc = out + (size_t)b * 19 * NPIX + 16 * NPIX + pix;
        if (apparel) {
            float t0 = 0.f, t1 = 0.f, t2 = 0.f;
            if (valid) {
                const float* tb = st + (size_t)b * 3 * HWn + pos;
                t0 = __ldg(tb);
                t1 = __ldg(tb + HWn);
                t2 = __ldg(tb + 2 * HWn);
            }
            oc[0 * NPIX] = t0;
            oc[1 * NPIX] = t1;
            oc[2 * NPIX] = t2;
        } else if (bg) {
            const float* ti = timg + (size_t)b * 3 * NPIX + pix;
            oc[0 * NPIX] = __ldg(ti);
            oc[1 * NPIX] = __ldg(ti + NPIX);
            oc[2 * NPIX] = __ldg(ti + 2 * NPIX);
        } else {
            oc[0 * NPIX] = 0.0f;
            oc[1 * NPIX] = 0.0f;
            oc[2 * NPIX] = 0.0f;
        }
    }
}

// ---------------------------------------------------------------------------
extern "C" void kernel_launch(void* const* d_in, const int* in_sizes, int n_in,
                              void* d_out, int out_size)
{
    const float* source_feature = (const float*)d_in[0];
    const float* target_feature = (const float*)d_in[1];
    const float* dense_pose     = (const float*)d_in[2];
    const float* source_texture = (const float*)d_in[3];
    const float* target_image   = (const float*)d_in[4];
    float* out = (float*)d_out;

    dim3 g(NPIX / 256, Bn, NGRP);
    k_split<<<g, 256>>>(source_feature, target_feature, dense_pose,
                        source_texture, target_image, out);
}